// round 13
// baseline (speedup 1.0000x reference)
#include <cuda_runtime.h>
#include <cstdint>

#define BATCH 64
#define TLEN  512
#define D     1024

// ---------------- scratch (device globals: no allocations allowed) ----------------
__device__ float g_ext[(size_t)TLEN * BATCH * D];   // 128 MB, layout [t][b][o]
__device__ float g_sbuf[2][BATCH * D];              // ping-pong: state + ext[t] combined
__device__ unsigned g_kbar[4 * 8 * 32];              // [m-group][k-group] counters, 128B apart

typedef unsigned long long ULL;

// ---------------- packed f32x2 helpers (sm_103a FFMA2 path) ----------------
static __device__ __forceinline__ ULL pack_dup(float w) {
    ULL r;
    asm("mov.b64 %0, {%1, %1};" : "=l"(r) : "f"(w));
    return r;
}
static __device__ __forceinline__ void fma2(ULL& d, ULL a, ULL b) {
    asm("fma.rn.f32x2 %0, %1, %2, %0;" : "+l"(d) : "l"(a), "l"(b));
}
static __device__ __forceinline__ void unpack2(ULL v, float& lo, float& hi) {
    asm("mov.b64 {%0, %1}, %2;" : "=f"(lo), "=f"(hi) : "l"(v));
}
static __device__ __forceinline__ uint32_t smem_u32(const void* p) {
    uint32_t a;
    asm("{ .reg .u64 t; cvta.to.shared.u64 t, %1; cvt.u32.u64 %0, t; }" : "=r"(a) : "l"(p));
    return a;
}

// ---------------- trivial zero kernels ----------------
__global__ void zero4_kernel(float4* __restrict__ p, int n4) {
    int i = blockIdx.x * blockDim.x + threadIdx.x;
    if (i < n4) p[i] = make_float4(0.f, 0.f, 0.f, 0.f);
}
__global__ void zero_misc_kernel() {
    int i = blockIdx.x * blockDim.x + threadIdx.x;
    if (i < 4 * 8 * 32) g_kbar[i] = 0u;
}

// ---------------- Phase A: ext[t][b][o] = sum_k x[m][k] * W_in[o][k], m=b*512+t --------
#define BM 128
#define BN 64
#define BK 32
#define PADA 134
#define PADB 68
#define ASTRIDE (BK * PADA)
#define BSTRIDE (BK * PADB)
#define EXT_SMEM ((2 * ASTRIDE + 2 * BSTRIDE) * 4)   // 51712 B

__global__ __launch_bounds__(256, 2) void ext_gemm_kernel(const float* __restrict__ X,
                                                          const float* __restrict__ Win) {
    extern __shared__ float esm[];
    float* As = esm;
    float* Bs = esm + 2 * ASTRIDE;

    const int tid = threadIdx.x;
    const int Mb = blockIdx.y * BM;
    const int Nb = blockIdx.x * BN;
    const int ty = tid >> 4, tx = tid & 15;
    const int m0 = ty * 8, n0 = tx * 4;

    ULL acc[4][4];
#pragma unroll
    for (int i = 0; i < 4; ++i)
#pragma unroll
        for (int j = 0; j < 4; ++j) acc[i][j] = 0ULL;

    const int ar = tid >> 3, ac = tid & 7;
    const int br = tid >> 2, bc = tid & 3;

    float4 ra[4], rb[2];
#pragma unroll
    for (int g = 0; g < 4; ++g)
        ra[g] = *(const float4*)&X[(size_t)(Mb + ar + g * 32) * D + ac * 4];
#pragma unroll
    for (int g = 0; g < 2; ++g)
        rb[g] = *(const float4*)&Win[(size_t)(Nb + br) * D + (bc + g * 4) * 4];
    {
#pragma unroll
        for (int g = 0; g < 4; ++g) {
            const int m = ar + g * 32;
            As[(ac * 4 + 0) * PADA + m] = ra[g].x;
            As[(ac * 4 + 1) * PADA + m] = ra[g].y;
            As[(ac * 4 + 2) * PADA + m] = ra[g].z;
            As[(ac * 4 + 3) * PADA + m] = ra[g].w;
        }
#pragma unroll
        for (int g = 0; g < 2; ++g) {
            const int cc = bc + g * 4;
            Bs[(cc * 4 + 0) * PADB + br] = rb[g].x;
            Bs[(cc * 4 + 1) * PADB + br] = rb[g].y;
            Bs[(cc * 4 + 2) * PADB + br] = rb[g].z;
            Bs[(cc * 4 + 3) * PADB + br] = rb[g].w;
        }
    }
    __syncthreads();

    for (int kt = 0; kt < D / BK; ++kt) {
        const int s = kt & 1;
        const float* Ac = As + s * ASTRIDE;
        const float* Bc = Bs + s * BSTRIDE;

        if (kt < D / BK - 1) {
            const int k0 = (kt + 1) * BK;
#pragma unroll
            for (int g = 0; g < 4; ++g)
                ra[g] = *(const float4*)&X[(size_t)(Mb + ar + g * 32) * D + k0 + ac * 4];
#pragma unroll
            for (int g = 0; g < 2; ++g)
                rb[g] = *(const float4*)&Win[(size_t)(Nb + br) * D + k0 + (bc + g * 4) * 4];
        }

#pragma unroll
        for (int kk = 0; kk < BK; ++kk) {
            const float* asr = &Ac[kk * PADA + m0];
            ULL a0 = *(const ULL*)(asr + 0);
            ULL a1 = *(const ULL*)(asr + 2);
            ULL a2 = *(const ULL*)(asr + 4);
            ULL a3 = *(const ULL*)(asr + 6);
            float4 bv = *(const float4*)&Bc[kk * PADB + n0];
            ULL b0 = pack_dup(bv.x);
            ULL b1 = pack_dup(bv.y);
            ULL b2 = pack_dup(bv.z);
            ULL b3 = pack_dup(bv.w);
            fma2(acc[0][0], a0, b0); fma2(acc[0][1], a0, b1); fma2(acc[0][2], a0, b2); fma2(acc[0][3], a0, b3);
            fma2(acc[1][0], a1, b0); fma2(acc[1][1], a1, b1); fma2(acc[1][2], a1, b2); fma2(acc[1][3], a1, b3);
            fma2(acc[2][0], a2, b0); fma2(acc[2][1], a2, b1); fma2(acc[2][2], a2, b2); fma2(acc[2][3], a2, b3);
            fma2(acc[3][0], a3, b0); fma2(acc[3][1], a3, b1); fma2(acc[3][2], a3, b2); fma2(acc[3][3], a3, b3);
        }

        if (kt < D / BK - 1) {
            float* An = As + (s ^ 1) * ASTRIDE;
            float* Bn = Bs + (s ^ 1) * BSTRIDE;
#pragma unroll
            for (int g = 0; g < 4; ++g) {
                const int m = ar + g * 32;
                An[(ac * 4 + 0) * PADA + m] = ra[g].x;
                An[(ac * 4 + 1) * PADA + m] = ra[g].y;
                An[(ac * 4 + 2) * PADA + m] = ra[g].z;
                An[(ac * 4 + 3) * PADA + m] = ra[g].w;
            }
#pragma unroll
            for (int g = 0; g < 2; ++g) {
                const int cc = bc + g * 4;
                Bn[(cc * 4 + 0) * PADB + br] = rb[g].x;
                Bn[(cc * 4 + 1) * PADB + br] = rb[g].y;
                Bn[(cc * 4 + 2) * PADB + br] = rb[g].z;
                Bn[(cc * 4 + 3) * PADB + br] = rb[g].w;
            }
        }
        __syncthreads();
    }

#pragma unroll
    for (int i = 0; i < 4; ++i) {
        float lo[4], hi[4];
#pragma unroll
        for (int j = 0; j < 4; ++j) unpack2(acc[i][j], lo[j], hi[j]);
        const int m = Mb + m0 + 2 * i;
        const int b0i = m >> 9, t0i = m & 511;
        const int b1i = (m + 1) >> 9, t1i = (m + 1) & 511;
        *(float4*)&g_ext[((size_t)t0i * BATCH + b0i) * D + Nb + n0] = make_float4(lo[0], lo[1], lo[2], lo[3]);
        *(float4*)&g_ext[((size_t)t1i * BATCH + b1i) * D + Nb + n0] = make_float4(hi[0], hi[1], hi[2], hi[3]);
    }
}

// ---------------- Phase B: persistent recurrence, fine-grained dataflow ----------------
// 256 threads, 8 warps. Warp w consumes state cols [128w,+128) — produced by exactly
// 4 CTAs (nx in [4w, 4w+4)). Producers signal per-(m-group, k-group) counters; each
// warp polls ONLY its counter, bulk-copies its warp-private sT k-slice (16 x 512B,
// per-warp mbarrier), and computes. No monolithic barrier; intra-CTA syncs only
// around the reduce. Compute identical to round 12 (crossbar-balanced 2m x 8n lanes).
#define NTILE 32
#define MTILE 16
#define WT_STRIDE 36
#define WT_FLOATS (D * WT_STRIDE)            // 36864
#define ST_STRIDE 1028
#define ST_FLOATS (MTILE * ST_STRIDE)        // 16448
#define RED_WSTR 544                         // 16 m * 34
#define RED_FLOATS (8 * RED_WSTR)            // 4352
#define OFF_MBAR ((WT_FLOATS + ST_FLOATS + RED_FLOATS) * 4)
#define PERS_SMEM (OFF_MBAR + 64)            // 8 mbarriers

__global__ __launch_bounds__(256, 1) void rnn_persistent(const float* __restrict__ Wr) {
    extern __shared__ float sm[];
    float* WT  = sm;                          // [1024 k][36]
    float* sT  = sm + WT_FLOATS;              // [16 m][1028]
    float* red = sm + WT_FLOATS + ST_FLOATS;  // [8 w][16 m * 34]

    const int tid  = threadIdx.x;
    const int w    = tid >> 5;
    const int lane = tid & 31;
    const int mg   = lane & 7;
    const int ng   = lane >> 3;
    const int n0   = ng * 8;
    const int kbase = w * 128;
    const int Nb = blockIdx.x * NTILE;
    const int Mb = blockIdx.y * MTILE;

    const uint32_t mbar0 = smem_u32(sm) + OFF_MBAR;
    const uint32_t my_mbar = mbar0 + 8u * (uint32_t)w;
    const uint32_t sT_a  = smem_u32(sT);

    // fine-grained counters: consume my (m-group, w); produce (m-group, nx>>2)
    unsigned* kctr = &g_kbar[((blockIdx.y * 8) + w) * 32];
    unsigned* sig  = &g_kbar[((blockIdx.y * 8) + (blockIdx.x >> 2)) * 32];

    // epilogue/reduce mapping
    const int em = tid >> 4;        // m row 0..15
    const int enp = tid & 15;       // n-pair 0..15

    // ---- stage WT[k][n] (transposed W slice; once for all steps) ----
    {
        const int n = tid & 31, kc = tid >> 5;
        const float* wp = Wr + (size_t)(Nb + n) * D + kc * 128;
        float* wt = WT + (size_t)(kc * 128) * WT_STRIDE + n;
#pragma unroll
        for (int j = 0; j < 32; ++j) {
            float4 v = __ldg((const float4*)(wp + 4 * j));
            float* dst = wt + (4 * j) * WT_STRIDE;
            dst[0] = v.x;
            dst[WT_STRIDE] = v.y;
            dst[2 * WT_STRIDE] = v.z;
            dst[3 * WT_STRIDE] = v.w;
        }
    }
    if (tid < 8) {
        asm volatile("mbarrier.init.shared.b64 [%0], %1;"
                     :: "r"(mbar0 + 8u * (uint32_t)tid), "r"(1) : "memory");
    }
    __syncthreads();

    for (int t = 0; t < TLEN; ++t) {
        // ---- prefetch ext[t+1] epilogue pair ----
        float2 e = make_float2(0.f, 0.f);
        if (t + 1 < TLEN) {
            const float* eb = g_ext + (size_t)(t + 1) * (BATCH * D) + (size_t)(Mb + em) * D + Nb + 2 * enp;
            e = __ldg((const float2*)eb);
        }

        // ---- per-warp: wait for MY 4 producers, then bulk-copy my k-slice ----
        if (lane == 0) {
            if (t > 0) {
                const unsigned target = 4u * (unsigned)t;
                unsigned v;
                do {
                    asm volatile("ld.acquire.gpu.u32 %0, [%1];" : "=r"(v) : "l"(kctr));
                } while (v < target);
            }
            const float* src = ((t == 0) ? (g_ext + (size_t)Mb * D)
                                         : (g_sbuf[t & 1] + (size_t)Mb * D)) + kbase;
            asm volatile("mbarrier.arrive.expect_tx.shared.b64 _, [%0], %1;"
                         :: "r"(my_mbar), "r"(8192) : "memory");
#pragma unroll
            for (int m = 0; m < MTILE; ++m) {
                asm volatile("cp.async.bulk.shared::cta.global.mbarrier::complete_tx::bytes [%0], [%1], %2, [%3];"
                             :: "r"(sT_a + (uint32_t)(m * ST_STRIDE + kbase) * 4u),
                                "l"(src + (size_t)m * D), "r"(512), "r"(my_mbar) : "memory");
            }
        }
        // all lanes of warp w wait on warp w's mbarrier
        {
            const uint32_t parity = (uint32_t)(t & 1);
            uint32_t done;
            do {
                asm volatile(
                    "{\n\t.reg .pred p;\n\t"
                    "mbarrier.try_wait.parity.acquire.cta.shared::cta.b64 p, [%1], %2, 0x989680;\n\t"
                    "selp.b32 %0, 1, 0, p;\n\t}"
                    : "=r"(done) : "r"(my_mbar), "r"(parity) : "memory");
            } while (!done);
        }

        // ---- compute: 2m x 8n per lane over this warp's 128-k slice ----
        ULL acc[8];
#pragma unroll
        for (int i = 0; i < 8; ++i) acc[i] = 0ULL;

        const float* a0p = sT + (size_t)mg * ST_STRIDE + kbase;
        const float* a1p = sT + (size_t)(mg + 8) * ST_STRIDE + kbase;
        const float* wtp = WT + (size_t)kbase * WT_STRIDE + n0;

#pragma unroll 8
        for (int i = 0; i < 64; ++i) {
            const int k2 = 2 * i;
            float2 av0 = *(const float2*)(a0p + k2);
            float2 av1 = *(const float2*)(a1p + k2);
            const float* wk = wtp + k2 * WT_STRIDE;
            ulonglong2 w0a = *(const ulonglong2*)(wk);
            ulonglong2 w0b = *(const ulonglong2*)(wk + 4);
            ulonglong2 w1a = *(const ulonglong2*)(wk + WT_STRIDE);
            ulonglong2 w1b = *(const ulonglong2*)(wk + WT_STRIDE + 4);
            ULL a00 = pack_dup(av0.x), a10 = pack_dup(av1.x);
            fma2(acc[0], a00, w0a.x); fma2(acc[1], a00, w0a.y);
            fma2(acc[2], a00, w0b.x); fma2(acc[3], a00, w0b.y);
            fma2(acc[4], a10, w0a.x); fma2(acc[5], a10, w0a.y);
            fma2(acc[6], a10, w0b.x); fma2(acc[7], a10, w0b.y);
            ULL a01 = pack_dup(av0.y), a11 = pack_dup(av1.y);
            fma2(acc[0], a01, w1a.x); fma2(acc[1], a01, w1a.y);
            fma2(acc[2], a01, w1b.x); fma2(acc[3], a01, w1b.y);
            fma2(acc[4], a11, w1a.x); fma2(acc[5], a11, w1a.y);
            fma2(acc[6], a11, w1b.x); fma2(acc[7], a11, w1b.y);
        }

        // ---- store per-warp partials ----
        {
            float* rw = red + w * RED_WSTR;
#pragma unroll
            for (int p = 0; p < 4; ++p) {
                *(ULL*)(rw + mg * 34 + n0 + 2 * p)       = acc[p];
                *(ULL*)(rw + (mg + 8) * 34 + n0 + 2 * p) = acc[4 + p];
            }
        }
        __syncthreads();

        // ---- reduce over 8 warps, ReLU, fuse ext[t+1], write combined buffer ----
        {
            const float* rp = red + em * 34 + 2 * enp;
            float s0 = 0.f, s1 = 0.f;
#pragma unroll
            for (int g = 0; g < 8; ++g) {
                float2 v = *(const float2*)(rp + g * RED_WSTR);
                s0 += v.x; s1 += v.y;
            }
            float v0 = fmaxf(s0, 0.f);
            float v1 = fmaxf(s1, 0.f);
            if (t + 1 < TLEN) { v0 += e.x; v1 += e.y; }
            float* sout = g_sbuf[(t + 1) & 1];
            float2 o = make_float2(v0, v1);
            __stcg((float2*)&sout[(size_t)(Mb + em) * D + Nb + 2 * enp], o);
        }
        __syncthreads();   // red reads done + STGs issued before signal

        if (tid == 0) {
            __threadfence();
            atomicAdd(sig, 1u);
        }
    }
}

// ---------------- final: out[:,0,:] = final state (g_sbuf[0], TLEN even) ----------------
__global__ void final_copy_kernel(float* __restrict__ out) {
    const int i = blockIdx.x * blockDim.x + threadIdx.x;   // < 65536
    const int b = i >> 10, o = i & 1023;
    out[(size_t)b * (TLEN * D) + o] = g_sbuf[0][i];
}

// ---------------- launch ----------------
extern "C" void kernel_launch(void* const* d_in, const int* in_sizes, int n_in,
                              void* d_out, int out_size) {
    const float* x     = (const float*)d_in[0];
    const float* W_in  = (const float*)d_in[1];
    const float* W_rec = (const float*)d_in[2];
    float* out = (float*)d_out;

    cudaFuncSetAttribute(rnn_persistent, cudaFuncAttributeMaxDynamicSharedMemorySize, PERS_SMEM);
    cudaFuncSetAttribute(ext_gemm_kernel, cudaFuncAttributeMaxDynamicSharedMemorySize, EXT_SMEM);

    // zero output (poisoned by harness) + dataflow counters
    zero4_kernel<<<(BATCH * TLEN * D / 4 + 255) / 256, 256>>>((float4*)out, BATCH * TLEN * D / 4);
    zero_misc_kernel<<<8, 128>>>();

    // Phase A: input projections for all timesteps (ext layout [t][b][o])
    ext_gemm_kernel<<<dim3(D / BN, (BATCH * TLEN) / BM), 256, EXT_SMEM>>>(x, W_in);

    // Phase B: full recurrence in one persistent kernel
    rnn_persistent<<<dim3(D / NTILE, BATCH / MTILE), 256, PERS_SMEM>>>(W_rec);

    // write final state into out[:,0,:]
    final_copy_kernel<<<(BATCH * D) / 256, 256>>>(out);
}